// round 8
// baseline (speedup 1.0000x reference)
#include <cuda_runtime.h>

// Problem constants
#define B_  64
#define H_  1024
#define I_  1024
#define BH  (B_ * H_)          // 65536
#define BHI ((size_t)BH * I_)  // 67108864
#define ROWS 4                 // (b,h) rows per block; consecutive bh share b

// ---------------------------------------------------------------------------
// Fused kernel, 4 rows per 256-thread block.
//   - cp.async (register-free) prefetch of all 4 Z rows + 4 F rows into smem,
//     issued before the GEMV so DRAM latency overlaps the serial chain
//   - phase 1 (L2-hot): gate GEMV partials, block reduction, parallel
//     epilogue (threads 0..3, scalars preloaded)
//   - phase 2: read smem -> FMA -> streaming store
// ---------------------------------------------------------------------------
__global__ void __launch_bounds__(256) fused_kernel(
    const float4* __restrict__ x4,     // [B, I/4]
    const float*  __restrict__ hidden_prev,
    const float4* __restrict__ Z,      // [BH, I/4]
    const float4* __restrict__ F,
    const float*  __restrict__ wz_state,
    const float*  __restrict__ wf_state,
    const float*  __restrict__ bz_state,
    const float*  __restrict__ bf_state,
    const float4* __restrict__ wmz4,   // [H, I/4]
    const float4* __restrict__ wmf4,
    const float*  __restrict__ wv_z,   // [H]
    const float*  __restrict__ wv_f,
    const float*  __restrict__ bias_z,
    const float*  __restrict__ bias_f,
    float*  __restrict__ out_cell,     // [B, H]
    float4* __restrict__ Zo,
    float4* __restrict__ Fo,
    float*  __restrict__ out_wz,
    float*  __restrict__ out_wf,
    float*  __restrict__ out_bz,
    float*  __restrict__ out_bf)
{
    __shared__ float4 zbuf[ROWS * 256];   // 16 KB
    __shared__ float4 fbuf[ROWS * 256];   // 16 KB
    __shared__ float  red[8][2 * ROWS];
    __shared__ float  coef[3][ROWS];

    const int bh0  = blockIdx.x * ROWS;
    const int b    = bh0 >> 10;
    const int h0   = bh0 & (H_ - 1);
    const int t    = threadIdx.x;
    const int wid  = t >> 5;
    const int lane = t & 31;

    const size_t row0 = (size_t)bh0 << 8;   // float4 offset of first row

    // ---- register-free prefetch of the DRAM stream into smem ----
    {
        unsigned zs = (unsigned)__cvta_generic_to_shared(&zbuf[t]);
        unsigned fs = (unsigned)__cvta_generic_to_shared(&fbuf[t]);
        #pragma unroll
        for (int r = 0; r < ROWS; ++r) {
            const float4* zg = Z + row0 + (size_t)(r << 8) + t;
            const float4* fg = F + row0 + (size_t)(r << 8) + t;
            asm volatile("cp.async.cg.shared.global [%0], [%1], 16;\n"
                         :: "r"(zs + r * 256 * 16), "l"(zg));
            asm volatile("cp.async.cg.shared.global [%0], [%1], 16;\n"
                         :: "r"(fs + r * 256 * 16), "l"(fg));
        }
        asm volatile("cp.async.commit_group;\n");
    }

    // ---- epilogue scalar preloads: threads 0..3, one row each ----
    float hp = 0.f, wzs = 0.f, wfs = 0.f, bzs = 0.f, bfs = 0.f;
    float vz = 0.f, vf = 0.f, bsz = 0.f, bsf = 0.f;
    if (t < ROWS) {
        const int bh = bh0 + t;
        const int h  = h0 + t;
        hp  = hidden_prev[bh];
        wzs = wz_state[bh];  wfs = wf_state[bh];
        bzs = bz_state[bh];  bfs = bf_state[bh];
        vz  = wv_z[h];       vf  = wv_f[h];
        bsz = bias_z[h];     bsf = bias_f[h];
    }

    // ---- phase 1: GEMV partials (x + wm rows, L2-hot) ----
    const float4 xv = __ldg(x4 + ((size_t)b << 8) + t);
    float pz[ROWS], pf[ROWS];
    #pragma unroll
    for (int r = 0; r < ROWS; ++r) {
        const float4 wzv = __ldg(wmz4 + ((size_t)(h0 + r) << 8) + t);
        const float4 wfv = __ldg(wmf4 + ((size_t)(h0 + r) << 8) + t);
        pz[r] = xv.x * wzv.x + xv.y * wzv.y + xv.z * wzv.z + xv.w * wzv.w;
        pf[r] = xv.x * wfv.x + xv.y * wfv.y + xv.z * wfv.z + xv.w * wfv.w;
    }
    #pragma unroll
    for (int o = 16; o > 0; o >>= 1) {
        #pragma unroll
        for (int r = 0; r < ROWS; ++r) {
            pz[r] += __shfl_xor_sync(0xffffffffu, pz[r], o);
            pf[r] += __shfl_xor_sync(0xffffffffu, pf[r], o);
        }
    }
    if (lane == 0) {
        #pragma unroll
        for (int r = 0; r < ROWS; ++r) {
            red[wid][r * 2]     = pz[r];
            red[wid][r * 2 + 1] = pf[r];
        }
    }
    __syncthreads();

    // ---- epilogue: threads 0..3 in parallel, operands already in regs ----
    if (t < ROWS) {
        float AZ = 0.f, AF = 0.f;
        #pragma unroll
        for (int w = 0; w < 8; ++w) {
            AZ += red[w][t * 2];
            AF += red[w][t * 2 + 1];
        }

        const int bh = bh0 + t;
        const float z    = tanhf(AZ + vz * hp + bsz);
        const float fpre = AF + vf * hp + bsf;
        const float f    = 1.f / (1.f + expf(-fpre));

        const float zf = (1.f - f) * (1.f - z * z);
        const float fz = (hp - z) * (1.f - f) * f;
        const float common = f + zf * vz + fz * vf;

        out_cell[bh] = hp * f + (1.f - f) * z;
        out_wz[bh]   = hp * zf + common * wzs;
        out_wf[bh]   = hp * fz + common * wfs;
        out_bz[bh]   = zf + common * bzs;
        out_bf[bh]   = fz + common * bfs;

        coef[0][t] = common;
        coef[1][t] = zf;
        coef[2][t] = fz;
    }

    // ---- wait for the DMA stream, then sync (also publishes coef) ----
    asm volatile("cp.async.wait_group 0;\n");
    __syncthreads();

    // ---- phase 2: smem -> FMA -> streaming store ----
    #pragma unroll
    for (int r = 0; r < ROWS; ++r) {
        const float4 zc = zbuf[r * 256 + t];
        const float4 fc = fbuf[r * 256 + t];

        const float c   = coef[0][r];
        const float czf = coef[1][r];
        const float cfz = coef[2][r];

        float4 zo, fo;
        zo.x = c * zc.x + czf * xv.x;
        zo.y = c * zc.y + czf * xv.y;
        zo.z = c * zc.z + czf * xv.z;
        zo.w = c * zc.w + czf * xv.w;
        fo.x = c * fc.x + cfz * xv.x;
        fo.y = c * fc.y + cfz * xv.y;
        fo.z = c * fc.z + cfz * xv.z;
        fo.w = c * fc.w + cfz * xv.w;

        const size_t off = row0 + (size_t)(r << 8) + t;
        __stcs(Zo + off, zo);
        __stcs(Fo + off, fo);
    }
}

// ---------------------------------------------------------------------------
extern "C" void kernel_launch(void* const* d_in, const int* in_sizes, int n_in,
                              void* d_out, int out_size)
{
    const float* x           = (const float*)d_in[0];
    const float* hidden_prev = (const float*)d_in[1];
    const float* Z_state     = (const float*)d_in[2];
    const float* F_state     = (const float*)d_in[3];
    const float* wz_state    = (const float*)d_in[4];
    const float* wf_state    = (const float*)d_in[5];
    const float* bz_state    = (const float*)d_in[6];
    const float* bf_state    = (const float*)d_in[7];
    const float* wm_z        = (const float*)d_in[8];
    const float* wm_f        = (const float*)d_in[9];
    const float* wv_z        = (const float*)d_in[10];
    const float* wv_f        = (const float*)d_in[11];
    const float* bias_z      = (const float*)d_in[12];
    const float* bias_f      = (const float*)d_in[13];

    float* out = (float*)d_out;
    // Output tuple layout: new_cell, Z_new, F_new, wz_new, wf_new, bz_new, bf_new
    float* o_cell = out;
    float* o_Z    = out + BH;
    float* o_F    = o_Z + BHI;
    float* o_wz   = o_F + BHI;
    float* o_wf   = o_wz + BH;
    float* o_bz   = o_wf + BH;
    float* o_bf   = o_bz + BH;

    fused_kernel<<<BH / ROWS, 256>>>(
        (const float4*)x, hidden_prev,
        (const float4*)Z_state, (const float4*)F_state,
        wz_state, wf_state, bz_state, bf_state,
        (const float4*)wm_z, (const float4*)wm_f,
        wv_z, wv_f, bias_z, bias_f,
        o_cell, (float4*)o_Z, (float4*)o_F,
        o_wz, o_wf, o_bz, o_bf);
}

// round 9
// speedup vs baseline: 1.0610x; 1.0610x over previous
#include <cuda_runtime.h>

// Problem constants
#define B_  64
#define H_  1024
#define I_  1024
#define BH  (B_ * H_)          // 65536
#define BHI ((size_t)BH * I_)  // 67108864
#define ROWS 4                 // (b,h) rows per block; consecutive bh share b

// ---------------------------------------------------------------------------
// Fused kernel, 4 rows per 256-thread block (R5 skeleton + single barrier):
//   - streaming Z/F loads for all 4 rows issued first (8 float4 in flight,
//     latency overlaps the GEMV serial chain)
//   - gate GEMV partials for 4 rows vs one register x chunk, warp-shuffle
//     reduce, ONE __syncthreads
//   - every warp redundantly computes the epilogue in lanes 0..3 and
//     broadcasts coef via shuffle: no second barrier, warps decouple and
//     issue their DRAM stores as soon as their own shuffles finish
// ---------------------------------------------------------------------------
__global__ void __launch_bounds__(256) fused_kernel(
    const float4* __restrict__ x4,     // [B, I/4]
    const float*  __restrict__ hidden_prev,
    const float4* __restrict__ Z,      // [BH, I/4]
    const float4* __restrict__ F,
    const float*  __restrict__ wz_state,
    const float*  __restrict__ wf_state,
    const float*  __restrict__ bz_state,
    const float*  __restrict__ bf_state,
    const float4* __restrict__ wmz4,   // [H, I/4]
    const float4* __restrict__ wmf4,
    const float*  __restrict__ wv_z,   // [H]
    const float*  __restrict__ wv_f,
    const float*  __restrict__ bias_z,
    const float*  __restrict__ bias_f,
    float*  __restrict__ out_cell,     // [B, H]
    float4* __restrict__ Zo,
    float4* __restrict__ Fo,
    float*  __restrict__ out_wz,
    float*  __restrict__ out_wf,
    float*  __restrict__ out_bz,
    float*  __restrict__ out_bf)
{
    __shared__ float red[8][2 * ROWS];   // [warp][r*2 + gate]

    const int bh0  = blockIdx.x * ROWS;
    const int b    = bh0 >> 10;
    const int h0   = bh0 & (H_ - 1);
    const int t    = threadIdx.x;
    const int wid  = t >> 5;
    const int lane = t & 31;

    const size_t row0 = (size_t)bh0 << 8;   // float4 offset of first row

    // ---- streaming loads for all 4 rows, issued first (touch-once) ----
    float4 zv[ROWS], fv[ROWS];
    #pragma unroll
    for (int r = 0; r < ROWS; ++r) {
        zv[r] = __ldcs(Z + row0 + (size_t)(r << 8) + t);
        fv[r] = __ldcs(F + row0 + (size_t)(r << 8) + t);
    }

    // ---- epilogue scalar preloads: lanes 0..3 of EVERY warp (L1 bcast) ----
    float hp = 0.f, wzs = 0.f, wfs = 0.f, bzs = 0.f, bfs = 0.f;
    float vz = 0.f, vf = 0.f, bsz = 0.f, bsf = 0.f;
    if (lane < ROWS) {
        const int bh = bh0 + lane;
        const int h  = h0 + lane;
        hp  = hidden_prev[bh];
        wzs = wz_state[bh];  wfs = wf_state[bh];
        bzs = bz_state[bh];  bfs = bf_state[bh];
        vz  = wv_z[h];       vf  = wv_f[h];
        bsz = bias_z[h];     bsf = bias_f[h];
    }

    // ---- GEMV partials: one x chunk, 4 wm_z/wm_f row chunks (L2-hot) ----
    const float4 xv = __ldg(x4 + ((size_t)b << 8) + t);
    float pz[ROWS], pf[ROWS];
    #pragma unroll
    for (int r = 0; r < ROWS; ++r) {
        const float4 wzv = __ldg(wmz4 + ((size_t)(h0 + r) << 8) + t);
        const float4 wfv = __ldg(wmf4 + ((size_t)(h0 + r) << 8) + t);
        pz[r] = xv.x * wzv.x + xv.y * wzv.y + xv.z * wzv.z + xv.w * wzv.w;
        pf[r] = xv.x * wfv.x + xv.y * wfv.y + xv.z * wfv.z + xv.w * wfv.w;
    }
    #pragma unroll
    for (int o = 16; o > 0; o >>= 1) {
        #pragma unroll
        for (int r = 0; r < ROWS; ++r) {
            pz[r] += __shfl_xor_sync(0xffffffffu, pz[r], o);
            pf[r] += __shfl_xor_sync(0xffffffffu, pf[r], o);
        }
    }
    if (lane == 0) {
        #pragma unroll
        for (int r = 0; r < ROWS; ++r) {
            red[wid][r * 2]     = pz[r];
            red[wid][r * 2 + 1] = pf[r];
        }
    }
    __syncthreads();   // the ONLY barrier

    // ---- epilogue: redundantly in lanes 0..3 of every warp ----
    float common = 0.f, zfc = 0.f, fzc = 0.f;
    if (lane < ROWS) {
        float AZ = 0.f, AF = 0.f;
        #pragma unroll
        for (int w = 0; w < 8; ++w) {
            AZ += red[w][lane * 2];
            AF += red[w][lane * 2 + 1];
        }

        const float z    = tanhf(AZ + vz * hp + bsz);
        const float fpre = AF + vf * hp + bsf;
        const float f    = 1.f / (1.f + expf(-fpre));

        zfc    = (1.f - f) * (1.f - z * z);
        fzc    = (hp - z) * (1.f - f) * f;
        common = f + zfc * vz + fzc * vf;

        if (wid == 0) {   // single writer for the small outputs
            const int bh = bh0 + lane;
            out_cell[bh] = hp * f + (1.f - f) * z;
            out_wz[bh]   = hp * zfc + common * wzs;
            out_wf[bh]   = hp * fzc + common * wfs;
            out_bz[bh]   = zfc + common * bzs;
            out_bf[bh]   = fzc + common * bfs;
        }
    }

    // ---- streaming FMA + stores; coef broadcast via intra-warp shuffle ----
    #pragma unroll
    for (int r = 0; r < ROWS; ++r) {
        const float c   = __shfl_sync(0xffffffffu, common, r);
        const float czf = __shfl_sync(0xffffffffu, zfc, r);
        const float cfz = __shfl_sync(0xffffffffu, fzc, r);

        float4 zo, fo;
        zo.x = c * zv[r].x + czf * xv.x;
        zo.y = c * zv[r].y + czf * xv.y;
        zo.z = c * zv[r].z + czf * xv.z;
        zo.w = c * zv[r].w + czf * xv.w;
        fo.x = c * fv[r].x + cfz * xv.x;
        fo.y = c * fv[r].y + cfz * xv.y;
        fo.z = c * fv[r].z + cfz * xv.z;
        fo.w = c * fv[r].w + cfz * xv.w;

        const size_t off = row0 + (size_t)(r << 8) + t;
        __stcs(Zo + off, zo);
        __stcs(Fo + off, fo);
    }
}

// ---------------------------------------------------------------------------
extern "C" void kernel_launch(void* const* d_in, const int* in_sizes, int n_in,
                              void* d_out, int out_size)
{
    const float* x           = (const float*)d_in[0];
    const float* hidden_prev = (const float*)d_in[1];
    const float* Z_state     = (const float*)d_in[2];
    const float* F_state     = (const float*)d_in[3];
    const float* wz_state    = (const float*)d_in[4];
    const float* wf_state    = (const float*)d_in[5];
    const float* bz_state    = (const float*)d_in[6];
    const float* bf_state    = (const float*)d_in[7];
    const float* wm_z        = (const float*)d_in[8];
    const float* wm_f        = (const float*)d_in[9];
    const float* wv_z        = (const float*)d_in[10];
    const float* wv_f        = (const float*)d_in[11];
    const float* bias_z      = (const float*)d_in[12];
    const float* bias_f      = (const float*)d_in[13];

    float* out = (float*)d_out;
    // Output tuple layout: new_cell, Z_new, F_new, wz_new, wf_new, bz_new, bf_new
    float* o_cell = out;
    float* o_Z    = out + BH;
    float* o_F    = o_Z + BHI;
    float* o_wz   = o_F + BHI;
    float* o_wf   = o_wz + BH;
    float* o_bz   = o_wf + BH;
    float* o_bf   = o_bz + BH;

    fused_kernel<<<BH / ROWS, 256>>>(
        (const float4*)x, hidden_prev,
        (const float4*)Z_state, (const float4*)F_state,
        wz_state, wf_state, bz_state, bf_state,
        (const float4*)wm_z, (const float4*)wm_f,
        wv_z, wv_f, bias_z, bias_f,
        o_cell, (float4*)o_Z, (float4*)o_F,
        o_wz, o_wf, o_bz, o_bf);
}

// round 10
// speedup vs baseline: 1.0612x; 1.0002x over previous
#include <cuda_runtime.h>

// Problem constants
#define B_  64
#define H_  1024
#define I_  1024
#define BH  (B_ * H_)          // 65536
#define BHI ((size_t)BH * I_)  // 67108864
#define ROWS 4                 // (b,h) rows per block; consecutive bh share b

// ---------------------------------------------------------------------------
// Fused kernel, 4 rows per 256-thread block, single barrier:
//   - streaming Z/F loads for all 4 rows issued first (8 float4 in flight,
//     latency overlaps the GEMV serial chain)
//   - gate GEMV partials for 4 rows vs one register x chunk, warp-shuffle
//     reduce, ONE __syncthreads
//   - every warp redundantly computes the epilogue in lanes 0..3 (scalar
//     operands loaded POST-barrier: they are L1-hot and keeping them out of
//     the GEMV phase cuts live registers -> 4 CTAs/SM instead of 3)
//   - coef broadcast via intra-warp shuffle; no second barrier
// ---------------------------------------------------------------------------
__global__ void __launch_bounds__(256, 4) fused_kernel(
    const float4* __restrict__ x4,     // [B, I/4]
    const float*  __restrict__ hidden_prev,
    const float4* __restrict__ Z,      // [BH, I/4]
    const float4* __restrict__ F,
    const float*  __restrict__ wz_state,
    const float*  __restrict__ wf_state,
    const float*  __restrict__ bz_state,
    const float*  __restrict__ bf_state,
    const float4* __restrict__ wmz4,   // [H, I/4]
    const float4* __restrict__ wmf4,
    const float*  __restrict__ wv_z,   // [H]
    const float*  __restrict__ wv_f,
    const float*  __restrict__ bias_z,
    const float*  __restrict__ bias_f,
    float*  __restrict__ out_cell,     // [B, H]
    float4* __restrict__ Zo,
    float4* __restrict__ Fo,
    float*  __restrict__ out_wz,
    float*  __restrict__ out_wf,
    float*  __restrict__ out_bz,
    float*  __restrict__ out_bf)
{
    __shared__ float red[8][2 * ROWS];   // [warp][r*2 + gate]

    const int bh0  = blockIdx.x * ROWS;
    const int b    = bh0 >> 10;
    const int h0   = bh0 & (H_ - 1);
    const int t    = threadIdx.x;
    const int wid  = t >> 5;
    const int lane = t & 31;

    const size_t row0 = (size_t)bh0 << 8;   // float4 offset of first row

    // ---- streaming loads for all 4 rows, issued first (touch-once) ----
    float4 zv[ROWS], fv[ROWS];
    #pragma unroll
    for (int r = 0; r < ROWS; ++r) {
        zv[r] = __ldcs(Z + row0 + (size_t)(r << 8) + t);
        fv[r] = __ldcs(F + row0 + (size_t)(r << 8) + t);
    }

    // ---- GEMV partials: one x chunk, 4 wm_z/wm_f row chunks (L2-hot) ----
    const float4 xv = __ldg(x4 + ((size_t)b << 8) + t);
    float pz[ROWS], pf[ROWS];
    #pragma unroll
    for (int r = 0; r < ROWS; ++r) {
        const float4 wzv = __ldg(wmz4 + ((size_t)(h0 + r) << 8) + t);
        const float4 wfv = __ldg(wmf4 + ((size_t)(h0 + r) << 8) + t);
        pz[r] = xv.x * wzv.x + xv.y * wzv.y + xv.z * wzv.z + xv.w * wzv.w;
        pf[r] = xv.x * wfv.x + xv.y * wfv.y + xv.z * wfv.z + xv.w * wfv.w;
    }
    #pragma unroll
    for (int o = 16; o > 0; o >>= 1) {
        #pragma unroll
        for (int r = 0; r < ROWS; ++r) {
            pz[r] += __shfl_xor_sync(0xffffffffu, pz[r], o);
            pf[r] += __shfl_xor_sync(0xffffffffu, pf[r], o);
        }
    }
    if (lane == 0) {
        #pragma unroll
        for (int r = 0; r < ROWS; ++r) {
            red[wid][r * 2]     = pz[r];
            red[wid][r * 2 + 1] = pf[r];
        }
    }
    __syncthreads();   // the ONLY barrier

    // ---- epilogue: redundantly in lanes 0..3 of every warp.
    //      scalar operands loaded here (post-barrier, L1-hot). ----
    float common = 0.f, zfc = 0.f, fzc = 0.f;
    if (lane < ROWS) {
        const int bh = bh0 + lane;
        const int h  = h0 + lane;

        float AZ = 0.f, AF = 0.f;
        #pragma unroll
        for (int w = 0; w < 8; ++w) {
            AZ += red[w][lane * 2];
            AF += red[w][lane * 2 + 1];
        }

        const float hp   = hidden_prev[bh];
        const float vz   = wv_z[h];
        const float vf   = wv_f[h];
        const float z    = tanhf(AZ + vz * hp + bias_z[h]);
        const float fpre = AF + vf * hp + bias_f[h];
        const float f    = 1.f / (1.f + expf(-fpre));

        zfc    = (1.f - f) * (1.f - z * z);
        fzc    = (hp - z) * (1.f - f) * f;
        common = f + zfc * vz + fzc * vf;

        if (wid == 0) {   // single writer for the small outputs
            out_cell[bh] = hp * f + (1.f - f) * z;
            out_wz[bh]   = hp * zfc + common * wz_state[bh];
            out_wf[bh]   = hp * fzc + common * wf_state[bh];
            out_bz[bh]   = zfc + common * bz_state[bh];
            out_bf[bh]   = fzc + common * bf_state[bh];
        }
    }

    // ---- streaming FMA + stores; coef broadcast via intra-warp shuffle ----
    #pragma unroll
    for (int r = 0; r < ROWS; ++r) {
        const float c   = __shfl_sync(0xffffffffu, common, r);
        const float czf = __shfl_sync(0xffffffffu, zfc, r);
        const float cfz = __shfl_sync(0xffffffffu, fzc, r);

        float4 zo, fo;
        zo.x = c * zv[r].x + czf * xv.x;
        zo.y = c * zv[r].y + czf * xv.y;
        zo.z = c * zv[r].z + czf * xv.z;
        zo.w = c * zv[r].w + czf * xv.w;
        fo.x = c * fv[r].x + cfz * xv.x;
        fo.y = c * fv[r].y + cfz * xv.y;
        fo.z = c * fv[r].z + cfz * xv.z;
        fo.w = c * fv[r].w + cfz * xv.w;

        const size_t off = row0 + (size_t)(r << 8) + t;
        __stcs(Zo + off, zo);
        __stcs(Fo + off, fo);
    }
}

// ---------------------------------------------------------------------------
extern "C" void kernel_launch(void* const* d_in, const int* in_sizes, int n_in,
                              void* d_out, int out_size)
{
    const float* x           = (const float*)d_in[0];
    const float* hidden_prev = (const float*)d_in[1];
    const float* Z_state     = (const float*)d_in[2];
    const float* F_state     = (const float*)d_in[3];
    const float* wz_state    = (const float*)d_in[4];
    const float* wf_state    = (const float*)d_in[5];
    const float* bz_state    = (const float*)d_in[6];
    const float* bf_state    = (const float*)d_in[7];
    const float* wm_z        = (const float*)d_in[8];
    const float* wm_f        = (const float*)d_in[9];
    const float* wv_z        = (const float*)d_in[10];
    const float* wv_f        = (const float*)d_in[11];
    const float* bias_z      = (const float*)d_in[12];
    const float* bias_f      = (const float*)d_in[13];

    float* out = (float*)d_out;
    // Output tuple layout: new_cell, Z_new, F_new, wz_new, wf_new, bz_new, bf_new
    float* o_cell = out;
    float* o_Z    = out + BH;
    float* o_F    = o_Z + BHI;
    float* o_wz   = o_F + BHI;
    float* o_wf   = o_wz + BH;
    float* o_bz   = o_wf + BH;
    float* o_bf   = o_bz + BH;

    fused_kernel<<<BH / ROWS, 256>>>(
        (const float4*)x, hidden_prev,
        (const float4*)Z_state, (const float4*)F_state,
        wz_state, wf_state, bz_state, bf_state,
        (const float4*)wm_z, (const float4*)wm_f,
        wv_z, wv_f, bias_z, bias_f,
        o_cell, (float4*)o_Z, (float4*)o_F,
        o_wz, o_wf, o_bz, o_bf);
}